// round 7
// baseline (speedup 1.0000x reference)
#include <cuda_runtime.h>
#include <cstdint>

#define THREADS 576
#define IN_DIM  2304
#define OUT_DIM 576
#define BATCH   16384
#define RS4     688                 // padded row stride in float4
#define CHUNK   6                   // rows per chunk
#define NBUF    3
#define NCTA    148
#define XBUF_F4 (CHUNK * RS4)       // 4128 float4 per buffer
#define SMEM_BYTES (NBUF * XBUF_F4 * 16)   // 198144

// Padded smem row layout (float4 indices within one x row):
//   seg1: 16 groups, stride 5  -> [0, 80)
//   seg2: 32 groups, stride 10 -> [80, 400)
//   seg3: 16 groups, stride 18 -> [400, 688)
__device__ __forceinline__ int pad_map(int f) {
    if (f < 64)  return f + (f >> 2);
    if (f < 320) return 80 + (f - 64) + (((f - 64) >> 3) << 1);
    return 400 + (f - 320) + (((f - 320) >> 4) << 1);
}

__device__ __forceinline__ void cpa16(uint32_t daddr, const void* src) {
    asm volatile("cp.async.cg.shared.global [%0], [%1], 16;\n" :: "r"(daddr), "l"(src));
}

// Three rows, one column pair each, over this thread's K-half.
// N4 f4 loads per row; one accumulator chain per output (6 outputs).
#define DOTPAIR3(N4)                                                         \
    {                                                                        \
        _Pragma("unroll")                                                    \
        for (int k4 = 0; k4 < (N4); k4++) {                                  \
            float4 u = xr0[xoff + 2 * k4 + h];                               \
            float4 v = xr1[xoff + 2 * k4 + h];                               \
            float4 t = xr2[xoff + 2 * k4 + h];                               \
            sA0 = fmaf(u.x, wA[4*k4+0], sA0);                                \
            sA0 = fmaf(u.y, wA[4*k4+1], sA0);                                \
            sA0 = fmaf(u.z, wA[4*k4+2], sA0);                                \
            sA0 = fmaf(u.w, wA[4*k4+3], sA0);                                \
            sB0 = fmaf(u.x, wB[4*k4+0], sB0);                                \
            sB0 = fmaf(u.y, wB[4*k4+1], sB0);                                \
            sB0 = fmaf(u.z, wB[4*k4+2], sB0);                                \
            sB0 = fmaf(u.w, wB[4*k4+3], sB0);                                \
            sA1 = fmaf(v.x, wA[4*k4+0], sA1);                                \
            sA1 = fmaf(v.y, wA[4*k4+1], sA1);                                \
            sA1 = fmaf(v.z, wA[4*k4+2], sA1);                                \
            sA1 = fmaf(v.w, wA[4*k4+3], sA1);                                \
            sB1 = fmaf(v.x, wB[4*k4+0], sB1);                                \
            sB1 = fmaf(v.y, wB[4*k4+1], sB1);                                \
            sB1 = fmaf(v.z, wB[4*k4+2], sB1);                                \
            sB1 = fmaf(v.w, wB[4*k4+3], sB1);                                \
            sA2 = fmaf(t.x, wA[4*k4+0], sA2);                                \
            sA2 = fmaf(t.y, wA[4*k4+1], sA2);                                \
            sA2 = fmaf(t.z, wA[4*k4+2], sA2);                                \
            sA2 = fmaf(t.w, wA[4*k4+3], sA2);                                \
            sB2 = fmaf(t.x, wB[4*k4+0], sB2);                                \
            sB2 = fmaf(t.y, wB[4*k4+1], sB2);                                \
            sB2 = fmaf(t.z, wB[4*k4+2], sB2);                                \
            sB2 = fmaf(t.w, wB[4*k4+3], sB2);                                \
        }                                                                    \
    }

extern "C" __global__ void __launch_bounds__(THREADS, 1)
tet_kernel(const float* __restrict__ x, const float* __restrict__ w,
           const float* __restrict__ bias, float* __restrict__ out)
{
    extern __shared__ __align__(16) float4 Xs[];          // [NBUF][CHUNK][RS4]

    const int tid = threadIdx.x;
    const int bid = blockIdx.x;

    // row partition: 16384 = 148*110 + 104
    const int row0  = bid * 110 + (bid < 104 ? bid : 104);
    const int nrows = 110 + (bid < 104 ? 1 : 0);
    const int nchunks = (nrows + CHUNK - 1) / CHUNK;      // 19

    const int h = tid & 1;          // K-half parity (partner = tid^1)

    // ---- role setup: tid<256 seg3 | tid<512 seg2 | else seg1 ----
    float wA[32], wB[32];
    int xoff, myCol;
    if (tid < 256) {
        const int p = tid >> 1, g3 = p >> 3, cp3 = p & 7;
        const int base = 9216 + g3 * 1024;
        #pragma unroll
        for (int k4 = 0; k4 < 8; k4++)
            #pragma unroll
            for (int i = 0; i < 4; i++) {
                int k = 8 * k4 + 4 * h + i;
                wA[4*k4+i] = w[base + k * 16 + cp3];
                wB[4*k4+i] = w[base + k * 16 + cp3 + 8];
            }
        xoff = 400 + 18 * g3;
        const int colA = 320 + g3 * 16 + cp3;
        myCol = h ? colA + 8 : colA;
    } else if (tid < 512) {
        const int p = (tid - 256) >> 1, g2 = p >> 2, cp2 = p & 3;
        const int base = 1024 + g2 * 256;
        #pragma unroll
        for (int k4 = 0; k4 < 4; k4++)
            #pragma unroll
            for (int i = 0; i < 4; i++) {
                int k = 8 * k4 + 4 * h + i;
                wA[4*k4+i] = w[base + k * 8 + cp2];
                wB[4*k4+i] = w[base + k * 8 + cp2 + 4];
            }
        xoff = 80 + 10 * g2;
        const int colA = 64 + g2 * 8 + cp2;
        myCol = h ? colA + 4 : colA;
    } else {
        const int p = (tid - 512) >> 1, g1 = p >> 1, cp1 = p & 1;
        const int base = g1 * 64;
        #pragma unroll
        for (int k4 = 0; k4 < 2; k4++)
            #pragma unroll
            for (int i = 0; i < 4; i++) {
                int k = 8 * k4 + 4 * h + i;
                wA[4*k4+i] = w[base + k * 4 + cp1];
                wB[4*k4+i] = w[base + k * 4 + cp1 + 2];
            }
        xoff = 5 * g1;
        const int colA = g1 * 4 + cp1;
        myCol = h ? colA + 2 : colA;
    }
    const float myBias = bias[myCol];

    // ---- staging: f = tid (static addresses), r = u ----
    const uint32_t xsAddr = (uint32_t)__cvta_generic_to_shared(Xs);
    const uint32_t dstPad = xsAddr + (uint32_t)pad_map(tid) * 16;
    const char* srcBase = (const char*)(x + (size_t)row0 * IN_DIM) + (size_t)tid * 16;

    auto stage = [&](int cc) {
        const uint32_t d0 = dstPad + (uint32_t)(cc % NBUF) * (XBUF_F4 * 16);
        const char* s0 = srcBase + (size_t)cc * (CHUNK * IN_DIM * 4);
        const int umax = min(CHUNK, nrows - cc * CHUNK);
        #pragma unroll
        for (int u = 0; u < CHUNK; u++)
            if (u < umax) cpa16(d0 + u * (RS4 * 16), s0 + (size_t)u * (IN_DIM * 4));
    };

    // depth-2 prefetch
    stage(0);
    asm volatile("cp.async.commit_group;\n");
    if (nchunks > 1) stage(1);
    asm volatile("cp.async.commit_group;\n");

    for (int c = 0; c < nchunks; c++) {
        // outstanding: {c, c+1}; drain c only
        asm volatile("cp.async.wait_group 1;\n");
        __syncthreads();   // chunk-c visible to all; compute(c-1) done before buf reuse
        if (c + 2 < nchunks) stage(c + 2);
        asm volatile("cp.async.commit_group;\n");   // uniform group count (may be empty)

        const float4* bufp = Xs + (size_t)(c % NBUF) * XBUF_F4;
        const int rmax = min(CHUNK, nrows - c * CHUNK);
        float* ob = out + (size_t)(row0 + c * CHUNK) * OUT_DIM;

        #pragma unroll
        for (int r = 0; r < CHUNK; r += 3) {
            if (r >= rmax) break;
            const float4* xr0 = bufp + r * RS4;
            const float4* xr1 = xr0 + RS4;     // in-bounds smem; stores guarded
            const float4* xr2 = xr1 + RS4;
            float sA0 = 0.f, sB0 = 0.f, sA1 = 0.f, sB1 = 0.f, sA2 = 0.f, sB2 = 0.f;
            if (tid < 256)      DOTPAIR3(8)
            else if (tid < 512) DOTPAIR3(4)
            else                DOTPAIR3(2)
            sA0 += __shfl_xor_sync(0xffffffffu, sA0, 1);
            sB0 += __shfl_xor_sync(0xffffffffu, sB0, 1);
            sA1 += __shfl_xor_sync(0xffffffffu, sA1, 1);
            sB1 += __shfl_xor_sync(0xffffffffu, sB1, 1);
            sA2 += __shfl_xor_sync(0xffffffffu, sA2, 1);
            sB2 += __shfl_xor_sync(0xffffffffu, sB2, 1);
            float r0v = (h ? sB0 : sA0) + myBias;
            float r1v = (h ? sB1 : sA1) + myBias;
            float r2v = (h ? sB2 : sA2) + myBias;
            ob[(size_t)r * OUT_DIM + myCol] = r0v;
            if (r + 1 < rmax) ob[(size_t)(r + 1) * OUT_DIM + myCol] = r1v;
            if (r + 2 < rmax) ob[(size_t)(r + 2) * OUT_DIM + myCol] = r2v;
        }
    }
}

extern "C" void kernel_launch(void* const* d_in, const int* in_sizes, int n_in,
                              void* d_out, int out_size)
{
    const float* x    = (const float*)d_in[0];
    const float* wflt = (const float*)d_in[1];
    const float* bias = (const float*)d_in[2];
    float* out        = (float*)d_out;

    cudaFuncSetAttribute(tet_kernel, cudaFuncAttributeMaxDynamicSharedMemorySize, SMEM_BYTES);
    tet_kernel<<<NCTA, THREADS, SMEM_BYTES>>>(x, wflt, bias, out);
}

// round 8
// speedup vs baseline: 1.0452x; 1.0452x over previous
#include <cuda_runtime.h>
#include <cstdint>

#define THREADS 576
#define IN_DIM  2304
#define OUT_DIM 576
#define BATCH   16384
#define RS4     688                 // padded row stride in float4
#define CHUNK   8                   // rows per chunk
#define NCTA    148
#define XBUF_F4 (CHUNK * RS4)       // 5504 float4 per buffer
#define SMEM_BYTES (2 * XBUF_F4 * 16)   // 176128

// Padded smem row layout (float4 indices within one x row):
//   seg1: 16 groups, stride 5  -> [0, 80)
//   seg2: 32 groups, stride 10 -> [80, 400)
//   seg3: 16 groups, stride 18 -> [400, 688)
__device__ __forceinline__ int pad_map(int f) {
    if (f < 64)  return f + (f >> 2);
    if (f < 320) return 80 + (f - 64) + (((f - 64) >> 3) << 1);
    return 400 + (f - 320) + (((f - 320) >> 4) << 1);
}

__device__ __forceinline__ void cpa16(uint32_t daddr, const void* src) {
    asm volatile("cp.async.cg.shared.global [%0], [%1], 16;\n" :: "r"(daddr), "l"(src));
}

// packed f32x2 helpers
#define FMA2(acc, a, b) \
    asm("fma.rn.f32x2 %0, %1, %2, %0;" : "+l"(acc) : "l"(a), "l"(b))
#define PACK2(p, lo, hi) \
    asm("mov.b64 %0, {%1, %2};" : "=l"(p) : "f"(lo), "f"(hi))
#define LDS_V2B64(lo, hi, addr) \
    asm("ld.shared.v2.b64 {%0, %1}, [%2];" : "=l"(lo), "=l"(hi) : "r"(addr))

__device__ __forceinline__ float hsum2(uint64_t p) {
    float lo, hi;
    asm("mov.b64 {%0, %1}, %2;" : "=f"(lo), "=f"(hi) : "l"(p));
    return lo + hi;
}

// Two rows x two columns over this thread's K-half, packed f32x2 math.
// Per k4: 2 LDS.128 (as v2.b64) + 8 FFMA2  (== 32 scalar MACs).
#define DOTPAIR2(N4)                                                         \
    {                                                                        \
        _Pragma("unroll")                                                    \
        for (int k4 = 0; k4 < (N4); k4++) {                                  \
            uint64_t u01, u23, v01, v23;                                     \
            LDS_V2B64(u01, u23, a0 + k4 * 32);                               \
            LDS_V2B64(v01, v23, a1 + k4 * 32);                               \
            FMA2(sA0, u01, wA2[2*k4]); FMA2(sA0, u23, wA2[2*k4+1]);          \
            FMA2(sB0, u01, wB2[2*k4]); FMA2(sB0, u23, wB2[2*k4+1]);          \
            FMA2(sA1, v01, wA2[2*k4]); FMA2(sA1, v23, wA2[2*k4+1]);          \
            FMA2(sB1, v01, wB2[2*k4]); FMA2(sB1, v23, wB2[2*k4+1]);          \
        }                                                                    \
    }

extern "C" __global__ void __launch_bounds__(THREADS, 1)
tet_kernel(const float* __restrict__ x, const float* __restrict__ w,
           const float* __restrict__ bias, float* __restrict__ out)
{
    extern __shared__ __align__(16) float4 Xs[];          // [2][CHUNK][RS4]

    const int tid = threadIdx.x;
    const int bid = blockIdx.x;

    // row partition: 16384 = 148*110 + 104
    const int row0  = bid * 110 + (bid < 104 ? bid : 104);
    const int nrows = 110 + (bid < 104 ? 1 : 0);
    const int nchunks = (nrows + CHUNK - 1) / CHUNK;      // 14

    const int h = tid & 1;          // K-half parity (partner = tid^1)

    // ---- role setup: tid<256 seg3 | tid<512 seg2 | else seg1 ----
    // W pre-packed into f32x2 pairs: wA2[2*k4+j] = {w_k, w_{k+1}} for
    // k = 8*k4 + 4*h + 2*j.
    uint64_t wA2[16], wB2[16];
    int xoff, myCol;
    if (tid < 256) {
        const int p = tid >> 1, g3 = p >> 3, cp3 = p & 7;
        const int base = 9216 + g3 * 1024;
        #pragma unroll
        for (int k4 = 0; k4 < 8; k4++)
            #pragma unroll
            for (int j = 0; j < 2; j++) {
                int k = 8 * k4 + 4 * h + 2 * j;
                PACK2(wA2[2*k4+j], w[base + k * 16 + cp3],     w[base + (k+1) * 16 + cp3]);
                PACK2(wB2[2*k4+j], w[base + k * 16 + cp3 + 8], w[base + (k+1) * 16 + cp3 + 8]);
            }
        xoff = 400 + 18 * g3;
        const int colA = 320 + g3 * 16 + cp3;
        myCol = h ? colA + 8 : colA;
    } else if (tid < 512) {
        const int p = (tid - 256) >> 1, g2 = p >> 2, cp2 = p & 3;
        const int base = 1024 + g2 * 256;
        #pragma unroll
        for (int k4 = 0; k4 < 4; k4++)
            #pragma unroll
            for (int j = 0; j < 2; j++) {
                int k = 8 * k4 + 4 * h + 2 * j;
                PACK2(wA2[2*k4+j], w[base + k * 8 + cp2],     w[base + (k+1) * 8 + cp2]);
                PACK2(wB2[2*k4+j], w[base + k * 8 + cp2 + 4], w[base + (k+1) * 8 + cp2 + 4]);
            }
        xoff = 80 + 10 * g2;
        const int colA = 64 + g2 * 8 + cp2;
        myCol = h ? colA + 4 : colA;
    } else {
        const int p = (tid - 512) >> 1, g1 = p >> 1, cp1 = p & 1;
        const int base = g1 * 64;
        #pragma unroll
        for (int k4 = 0; k4 < 2; k4++)
            #pragma unroll
            for (int j = 0; j < 2; j++) {
                int k = 8 * k4 + 4 * h + 2 * j;
                PACK2(wA2[2*k4+j], w[base + k * 4 + cp1],     w[base + (k+1) * 4 + cp1]);
                PACK2(wB2[2*k4+j], w[base + k * 4 + cp1 + 2], w[base + (k+1) * 4 + cp1 + 2]);
            }
        xoff = 5 * g1;
        const int colA = g1 * 4 + cp1;
        myCol = h ? colA + 2 : colA;
    }
    const float myBias = bias[myCol];

    // ---- staging: f = tid (static addresses), r = u ----
    const uint32_t xsAddr = (uint32_t)__cvta_generic_to_shared(Xs);
    const uint32_t dstPad = xsAddr + (uint32_t)pad_map(tid) * 16;
    const char* srcBase = (const char*)(x + (size_t)row0 * IN_DIM) + (size_t)tid * 16;

    auto stage = [&](int cc) {
        const uint32_t d0 = dstPad + (uint32_t)(cc & 1) * (XBUF_F4 * 16);
        const char* s0 = srcBase + (size_t)cc * (CHUNK * IN_DIM * 4);
        const int umax = min(CHUNK, nrows - cc * CHUNK);
        #pragma unroll
        for (int u = 0; u < CHUNK; u++)
            if (u < umax) cpa16(d0 + u * (RS4 * 16), s0 + (size_t)u * (IN_DIM * 4));
    };

    // this thread's smem byte offset of its first K-half float4
    const uint32_t myXBase = xsAddr + (uint32_t)(xoff + h) * 16;

    stage(0);
    asm volatile("cp.async.commit_group;\n");

    for (int c = 0; c < nchunks; c++) {
        asm volatile("cp.async.wait_group 0;\n");
        __syncthreads();   // chunk-c visible; compute(c-1) reads done before reuse
        if (c + 1 < nchunks) {
            stage(c + 1);
            asm volatile("cp.async.commit_group;\n");
        }

        const uint32_t bufAddr = myXBase + (uint32_t)(c & 1) * (XBUF_F4 * 16);
        const int rmax = min(CHUNK, nrows - c * CHUNK);
        float* ob = out + (size_t)(row0 + c * CHUNK) * OUT_DIM;

        #pragma unroll
        for (int r = 0; r < CHUNK; r += 2) {
            if (r >= rmax) break;
            const uint32_t a0 = bufAddr + (uint32_t)r * (RS4 * 16);
            const uint32_t a1 = a0 + (RS4 * 16);   // smem in-bounds; store guarded
            uint64_t sA0 = 0, sB0 = 0, sA1 = 0, sB1 = 0;
            if (tid < 256)      DOTPAIR2(8)
            else if (tid < 512) DOTPAIR2(4)
            else                DOTPAIR2(2)
            float fA0 = hsum2(sA0), fB0 = hsum2(sB0);
            float fA1 = hsum2(sA1), fB1 = hsum2(sB1);
            fA0 += __shfl_xor_sync(0xffffffffu, fA0, 1);
            fB0 += __shfl_xor_sync(0xffffffffu, fB0, 1);
            fA1 += __shfl_xor_sync(0xffffffffu, fA1, 1);
            fB1 += __shfl_xor_sync(0xffffffffu, fB1, 1);
            float r0v = (h ? fB0 : fA0) + myBias;
            float r1v = (h ? fB1 : fA1) + myBias;
            ob[(size_t)r * OUT_DIM + myCol] = r0v;
            if (r + 1 < rmax) ob[(size_t)(r + 1) * OUT_DIM + myCol] = r1v;
        }
    }
}

extern "C" void kernel_launch(void* const* d_in, const int* in_sizes, int n_in,
                              void* d_out, int out_size)
{
    const float* x    = (const float*)d_in[0];
    const float* wflt = (const float*)d_in[1];
    const float* bias = (const float*)d_in[2];
    float* out        = (float*)d_out;

    cudaFuncSetAttribute(tet_kernel, cudaFuncAttributeMaxDynamicSharedMemorySize, SMEM_BYTES);
    tet_kernel<<<NCTA, THREADS, SMEM_BYTES>>>(x, wflt, bias, out);
}